// round 12
// baseline (speedup 1.0000x reference)
#include <cuda_runtime.h>
#include <cuda_fp16.h>
#include <cuda_fp8.h>
#include <stdint.h>

#define H_DIM 32
#define D_DIM 128
#define BM 128
#define BN 64
#define ROWP 136
#define SM_SCALE 0.08838834764831845f
#define LOG2E 1.4426950408889634f
#define SHIFT 14.0f
#define MAXTOT (4096*32*128)
#define SMEMSZ (2 * 256 * ROWP * 2)

__device__ __align__(16) __half g_kh[MAXTOT];
__device__ __align__(16) __half g_vh[MAXTOT];
__device__ unsigned g_absmax[3] = {0u, 0u, 0u};
__device__ unsigned g_kmax[128] = {};

__device__ __forceinline__ unsigned sptr(const void* p) {
    return (unsigned)__cvta_generic_to_shared(p);
}
__device__ __forceinline__ float ex2(float x) {
    float y; asm("ex2.approx.ftz.f32 %0,%1;" : "=f"(y) : "f"(x)); return y;
}
__device__ __forceinline__ void cpa16(unsigned s, const void* g) {
    asm volatile("cp.async.cg.shared.global [%0],[%1],16;" :: "r"(s), "l"(g));
}
__device__ __forceinline__ void ldsm4(uint32_t& r0, uint32_t& r1, uint32_t& r2, uint32_t& r3, unsigned a) {
    asm volatile("ldmatrix.sync.aligned.m8n8.x4.shared.b16 {%0,%1,%2,%3},[%4];"
                 : "=r"(r0), "=r"(r1), "=r"(r2), "=r"(r3) : "r"(a));
}
__device__ __forceinline__ void ldsm4t(uint32_t& r0, uint32_t& r1, uint32_t& r2, uint32_t& r3, unsigned a) {
    asm volatile("ldmatrix.sync.aligned.m8n8.x4.trans.shared.b16 {%0,%1,%2,%3},[%4];"
                 : "=r"(r0), "=r"(r1), "=r"(r2), "=r"(r3) : "r"(a));
}
__device__ __forceinline__ void mma16816(float* c, const uint32_t* a, const uint32_t* b) {
    asm volatile("mma.sync.aligned.m16n8k16.row.col.f32.f16.f16.f32 "
                 "{%0,%1,%2,%3},{%4,%5,%6,%7},{%8,%9},{%0,%1,%2,%3};"
                 : "+f"(c[0]), "+f"(c[1]), "+f"(c[2]), "+f"(c[3])
                 : "r"(a[0]), "r"(a[1]), "r"(a[2]), "r"(a[3]), "r"(b[0]), "r"(b[1]));
}

__global__ void absmax_kernel(const float* __restrict__ q, const float* __restrict__ k,
                              const float* __restrict__ v, int n) {
    const float* p = blockIdx.y == 0 ? q : (blockIdx.y == 1 ? k : v);
    int n4 = n >> 2;
    float m = 0.f;
    for (int i = blockIdx.x * blockDim.x + threadIdx.x; i < n4; i += gridDim.x * blockDim.x) {
        float4 x = ((const float4*)p)[i];
        m = fmaxf(m, fmaxf(fmaxf(fabsf(x.x), fabsf(x.y)), fmaxf(fabsf(x.z), fabsf(x.w))));
    }
    #pragma unroll
    for (int o = 16; o; o >>= 1) m = fmaxf(m, __shfl_xor_sync(0xffffffffu, m, o));
    if ((threadIdx.x & 31) == 0) atomicMax(&g_absmax[blockIdx.y], __float_as_uint(m));
}

__device__ __forceinline__ __half qd(float x, float inv) {
    __nv_fp8_storage_t f8 = __nv_cvt_float_to_fp8(x * inv, __NV_SATFINITE, __NV_E4M3);
    __half_raw hr = __nv_cvt_fp8_to_halfraw(f8, __NV_E4M3);
    return *reinterpret_cast<__half*>(&hr);
}

// streaming quantize + transpose for K and V only (Q is fused into fa)
__global__ void quant_kernel(const float* __restrict__ k, const float* __restrict__ v,
                             int total, int S) {
    int t = blockIdx.y + 1;
    const float* src = t == 1 ? k : v;
    __half* dst = t == 1 ? g_kh : g_vh;
    float inv = 448.0f / __uint_as_float(g_absmax[t]);
    size_t i = (size_t)blockIdx.x * blockDim.x + threadIdx.x;
    size_t n4 = ((size_t)total << 12) >> 2;
    if (i >= n4) return;
    float4 x = ((const float4*)src)[i];
    size_t e0 = i << 2;
    int token = (int)(e0 >> 12);
    int rem = (int)(e0 & 4095);
    int hh = rem >> 7;
    int d = rem & 127;
    int bb = token / S;
    int s = token - bb * S;
    size_t o = (((size_t)(bb * H_DIM + hh) * S + s) << 7) + d;
    __half rr[4];
    rr[0] = qd(x.x, inv); rr[1] = qd(x.y, inv);
    rr[2] = qd(x.z, inv); rr[3] = qd(x.w, inv);
    *(uint2*)(dst + o) = *(uint2*)rr;
}

// per-bh max K row norm: 16 threads per row, uint4 loads, 1 atomic per block
__global__ void kmax_kernel(int S) {
    __shared__ float sm[16];
    const int tid = threadIdx.x;
    const int row = blockIdx.x * 16 + (tid >> 4);
    const int seg = (tid & 15) * 8;
    uint4 u = *(const uint4*)(g_kh + (size_t)row * D_DIM + seg);
    const __half2* hp = (const __half2*)&u;
    float ss = 0.f;
    #pragma unroll
    for (int i = 0; i < 4; i++) {
        float2 f = __half22float2(hp[i]);
        ss += f.x * f.x + f.y * f.y;
    }
    #pragma unroll
    for (int o = 1; o < 16; o <<= 1) ss += __shfl_xor_sync(0xffffffffu, ss, o);
    if ((tid & 15) == 0) sm[tid >> 4] = ss;
    __syncthreads();
    if (tid == 0) {
        float m = sm[0];
        #pragma unroll
        for (int i = 1; i < 16; i++) m = fmaxf(m, sm[i]);
        atomicMax(&g_kmax[row / S], __float_as_uint(sqrtf(m)));
    }
}

__global__ __launch_bounds__(256, 1) void fa_kernel(float* __restrict__ out,
                                                    const float* __restrict__ qsrc, int S) {
    extern __shared__ __half smdyn[];
    __half (*KS)[ROWP] = (__half(*)[ROWP])smdyn;                    // 4 stages x 64 rows
    __half (*VS)[ROWP] = (__half(*)[ROWP])(smdyn + 256 * ROWP);

    const int bh = blockIdx.y;
    const int b = bh >> 5;
    const int h = bh & 31;
    const int qtile = blockIdx.x;
    const int q0 = qtile * BM;

    const size_t bhoff = (size_t)bh * S * D_DIM;
    const __half* Kg = g_kh + bhoff;
    const __half* Vg = g_vh + bhoff;

    const int tid = threadIdx.x;
    const int warp = tid >> 5;
    const int lane = tid & 31;
    const int l8 = lane & 7;
    const int g = lane >> 3;
    const int m0 = warp * 16;
    const float NEG_INF = __int_as_float(0xff800000);

    const float aq = __uint_as_float(g_absmax[0]) / 448.0f;
    const float ak = __uint_as_float(g_absmax[1]) / 448.0f;
    const float av = __uint_as_float(g_absmax[2]) / 448.0f;
    const float c1 = aq * ak * SM_SCALE * LOG2E;
    const float km = __uint_as_float(g_kmax[bh]);

    const int row0g = q0 + m0 + (lane >> 2);
    const int row1g = row0g + 8;

    // ---- fused Q: load fp32, quantize e4m3, store unscaled fp16 into KS rows 0..127 ----
    {
        const float invq = 448.0f / __uint_as_float(g_absmax[0]);
        const float* Qf = qsrc + ((size_t)(b * S + q0) * H_DIM + h) * D_DIM;
        #pragma unroll
        for (int it = 0; it < 16; it++) {
            int idx = tid + it * 256;
            int r = idx >> 5;
            int c4 = (idx & 31) * 4;
            float4 x = *(const float4*)(Qf + (size_t)r * H_DIM * D_DIM + c4);
            __half rr[4];
            rr[0] = qd(x.x, invq); rr[1] = qd(x.y, invq);
            rr[2] = qd(x.z, invq); rr[3] = qd(x.w, invq);
            *(uint2*)&KS[r][c4] = *(uint2*)rr;
        }
    }
    __syncthreads();
    uint32_t qf[8][4];
    #pragma unroll
    for (int kt = 0; kt < 8; kt++) {
        unsigned a = sptr(&KS[m0 + ((g & 1) << 3) + l8][kt * 16 + ((g & 2) << 2)]);
        ldsm4(qf[kt][0], qf[kt][1], qf[kt][2], qf[kt][3], a);
    }
    __syncthreads();

    // ---- in-register Q row norms ----
    float ss0 = 0.f, ss1 = 0.f;
    #pragma unroll
    for (int kt = 0; kt < 8; kt++) {
        float2 f0 = __half22float2(*(__half2*)&qf[kt][0]);
        float2 f1 = __half22float2(*(__half2*)&qf[kt][1]);
        float2 f2 = __half22float2(*(__half2*)&qf[kt][2]);
        float2 f3 = __half22float2(*(__half2*)&qf[kt][3]);
        ss0 += f0.x * f0.x + f0.y * f0.y + f2.x * f2.x + f2.y * f2.y;
        ss1 += f1.x * f1.x + f1.y * f1.y + f3.x * f3.x + f3.y * f3.y;
    }
    ss0 += __shfl_xor_sync(0xffffffffu, ss0, 1);
    ss0 += __shfl_xor_sync(0xffffffffu, ss0, 2);
    ss1 += __shfl_xor_sync(0xffffffffu, ss1, 1);
    ss1 += __shfl_xor_sync(0xffffffffu, ss1, 2);
    const float cadd0 = SHIFT - sqrtf(ss0) * km * c1 * 1.0001f;
    const float cadd1 = SHIFT - sqrtf(ss1) * km * c1 * 1.0001f;

    const int ntiles = 2 * qtile + 2;   // always even

    // ---- prologue: prefetch pair 0 ----
    {
        #pragma unroll
        for (int it = 0; it < 8; it++) {
            int idx = tid + it * 256;
            int r = idx >> 4;
            int c = (idx & 15) * 8;
            cpa16(sptr(&KS[r][c]), Kg + (size_t)r * D_DIM + c);
            cpa16(sptr(&VS[r][c]), Vg + (size_t)r * D_DIM + c);
        }
        asm volatile("cp.async.commit_group;");
    }

    float oacc[16][4];
    #pragma unroll
    for (int n = 0; n < 16; n++)
        #pragma unroll
        for (int e = 0; e < 4; e++) oacc[n][e] = 0.f;
    float lrow0 = 0.f, lrow1 = 0.f;

    for (int jj = 0; jj < ntiles; jj += 2) {
        const int stage = (jj >> 1) & 1;
        if (jj + 2 < ntiles) {
            const __half* Kj = Kg + (size_t)(jj + 2) * BN * D_DIM;
            const __half* Vj = Vg + (size_t)(jj + 2) * BN * D_DIM;
            const int nx = (stage ^ 1) * 128;
            #pragma unroll
            for (int it = 0; it < 8; it++) {
                int idx = tid + it * 256;
                int r = idx >> 4;
                int c = (idx & 15) * 8;
                cpa16(sptr(&KS[nx + r][c]), Kj + (size_t)r * D_DIM + c);
                cpa16(sptr(&VS[nx + r][c]), Vj + (size_t)r * D_DIM + c);
            }
            asm volatile("cp.async.commit_group;");
            asm volatile("cp.async.wait_group 1;");
        } else {
            asm volatile("cp.async.wait_group 0;");
        }
        __syncthreads();

        for (int j2 = 0; j2 < 2; j2++) {
            const int j = jj + j2;
            const int kb = stage * 128 + j2 * BN;
            const bool fullSkip = (j * BN > q0 + m0 + 15);
            if (fullSkip) continue;

            // ---- S = Q @ K^T  (qq outer: 8 independent accumulator chains) ----
            float sacc[8][4];
            #pragma unroll
            for (int n8 = 0; n8 < 8; n8++)
                #pragma unroll
                for (int e = 0; e < 4; e++) sacc[n8][e] = 0.f;

            #pragma unroll
            for (int qq = 0; qq < 4; qq++) {
                uint32_t kbf[8][2][2];   // [n8][kt-sub][reg]
                #pragma unroll
                for (int n8 = 0; n8 < 8; n8++) {
                    unsigned a = sptr(&KS[kb + (n8 << 3) + l8][qq * 32 + (g << 3)]);
                    ldsm4(kbf[n8][0][0], kbf[n8][0][1], kbf[n8][1][0], kbf[n8][1][1], a);
                }
                #pragma unroll
                for (int n8 = 0; n8 < 8; n8++)
                    mma16816(sacc[n8], qf[2 * qq], kbf[n8][0]);
                #pragma unroll
                for (int n8 = 0; n8 < 8; n8++)
                    mma16816(sacc[n8], qf[2 * qq + 1], kbf[n8][1]);
            }

            // ---- causal mask (only near-diagonal warp tiles) ----
            if (j * BN + BN - 1 > q0 + m0) {
                const int col0 = j * BN + ((lane & 3) << 1);
                #pragma unroll
                for (int n8 = 0; n8 < 8; n8++)
                    #pragma unroll
                    for (int e = 0; e < 4; e++) {
                        int col = col0 + (n8 << 3) + (e & 1);
                        int row = (e & 2) ? row1g : row0g;
                        if (col > row) sacc[n8][e] = NEG_INF;
                    }
            }

            // ---- fixed-bound softmax: no max, no rescale ----
            float ps0 = 0.f, ps1 = 0.f;
            uint32_t pf[4][4];
            #pragma unroll
            for (int n8 = 0; n8 < 8; n8++) {
                float p0 = ex2(fmaf(sacc[n8][0], c1, cadd0));
                float p1 = ex2(fmaf(sacc[n8][1], c1, cadd0));
                float p2 = ex2(fmaf(sacc[n8][2], c1, cadd1));
                float p3 = ex2(fmaf(sacc[n8][3], c1, cadd1));
                ps0 += p0 + p1;
                ps1 += p2 + p3;
                __half2 h01 = __floats2half2_rn(p0, p1);
                __half2 h23 = __floats2half2_rn(p2, p3);
                int kt = n8 >> 1;
                if (n8 & 1) {
                    pf[kt][2] = *reinterpret_cast<uint32_t*>(&h01);
                    pf[kt][3] = *reinterpret_cast<uint32_t*>(&h23);
                } else {
                    pf[kt][0] = *reinterpret_cast<uint32_t*>(&h01);
                    pf[kt][1] = *reinterpret_cast<uint32_t*>(&h23);
                }
            }
            lrow0 += ps0;
            lrow1 += ps1;

            // ---- O += P @ V ----
            #pragma unroll
            for (int kt = 0; kt < 4; kt++) {
                int k0 = kt << 4;
                #pragma unroll
                for (int e = 0; e < 8; e++) {
                    uint32_t r0, r1, r2, r3;
                    unsigned a = sptr(&VS[kb + k0 + ((g & 1) << 3) + l8][(e << 4) + ((g & 2) << 2)]);
                    ldsm4t(r0, r1, r2, r3, a);
                    uint32_t vb0[2] = {r0, r1}, vb1[2] = {r2, r3};
                    mma16816(oacc[2 * e], pf[kt], vb0);
                    mma16816(oacc[2 * e + 1], pf[kt], vb1);
                }
            }
        }
        __syncthreads();
    }

    // ---- epilogue ----
    lrow0 += __shfl_xor_sync(0xffffffffu, lrow0, 1);
    lrow0 += __shfl_xor_sync(0xffffffffu, lrow0, 2);
    lrow1 += __shfl_xor_sync(0xffffffffu, lrow1, 1);
    lrow1 += __shfl_xor_sync(0xffffffffu, lrow1, 2);
    float i0 = av / lrow0;
    float i1 = av / lrow1;
    size_t base0 = ((size_t)(b * S + row0g) * H_DIM + h) * D_DIM;
    size_t base1 = base0 + (size_t)8 * H_DIM * D_DIM;
    #pragma unroll
    for (int n = 0; n < 16; n++) {
        int col = (n << 3) + ((lane & 3) << 1);
        float2 v0 = {oacc[n][0] * i0, oacc[n][1] * i0};
        float2 v1 = {oacc[n][2] * i1, oacc[n][3] * i1};
        *(float2*)(out + base0 + col) = v0;
        *(float2*)(out + base1 + col) = v1;
    }
}

extern "C" void kernel_launch(void* const* d_in, const int* in_sizes, int n_in,
                              void* d_out, int out_size) {
    const float* q = (const float*)d_in[0];
    const float* k = (const float*)d_in[1];
    const float* v = (const float*)d_in[2];
    int n = in_sizes[0];
    int B = in_sizes[3] - 1;
    int total = n / (H_DIM * D_DIM);
    int S = total / B;
    int rows = total * H_DIM;

    cudaFuncSetAttribute(fa_kernel, cudaFuncAttributeMaxDynamicSharedMemorySize, SMEMSZ);

    absmax_kernel<<<dim3(296, 3), 256>>>(q, k, v, n);
    int n4 = n >> 2;
    quant_kernel<<<dim3((n4 + 255) / 256, 2), 256>>>(k, v, total, S);
    kmax_kernel<<<rows / 16, 256>>>(S);
    fa_kernel<<<dim3(S / BM, B * H_DIM), 256, SMEMSZ>>>((float*)d_out, q, S);
}

// round 13
// speedup vs baseline: 1.0180x; 1.0180x over previous
#include <cuda_runtime.h>
#include <cuda_fp16.h>
#include <cuda_fp8.h>
#include <stdint.h>

#define H_DIM 32
#define D_DIM 128
#define BM 128
#define BN 64
#define ROWP 136
#define SM_SCALE 0.08838834764831845f
#define LOG2E 1.4426950408889634f
#define SHIFT 14.0f
#define MAXTOT (4096*32*128)
#define SMEMSZ (2 * 256 * ROWP * 2)

__device__ __align__(16) __half g_kh[MAXTOT];
__device__ __align__(16) __half g_vh[MAXTOT];
__device__ unsigned g_absmax[3] = {0u, 0u, 0u};
__device__ unsigned g_kmax[128] = {};

__device__ __forceinline__ unsigned sptr(const void* p) {
    return (unsigned)__cvta_generic_to_shared(p);
}
__device__ __forceinline__ float ex2(float x) {
    float y; asm("ex2.approx.ftz.f32 %0,%1;" : "=f"(y) : "f"(x)); return y;
}
__device__ __forceinline__ void cpa16(unsigned s, const void* g) {
    asm volatile("cp.async.cg.shared.global [%0],[%1],16;" :: "r"(s), "l"(g));
}
__device__ __forceinline__ void ldsm4(uint32_t& r0, uint32_t& r1, uint32_t& r2, uint32_t& r3, unsigned a) {
    asm volatile("ldmatrix.sync.aligned.m8n8.x4.shared.b16 {%0,%1,%2,%3},[%4];"
                 : "=r"(r0), "=r"(r1), "=r"(r2), "=r"(r3) : "r"(a));
}
__device__ __forceinline__ void ldsm4t(uint32_t& r0, uint32_t& r1, uint32_t& r2, uint32_t& r3, unsigned a) {
    asm volatile("ldmatrix.sync.aligned.m8n8.x4.trans.shared.b16 {%0,%1,%2,%3},[%4];"
                 : "=r"(r0), "=r"(r1), "=r"(r2), "=r"(r3) : "r"(a));
}
__device__ __forceinline__ void mma16816(float* c, const uint32_t* a, const uint32_t* b) {
    asm volatile("mma.sync.aligned.m16n8k16.row.col.f32.f16.f16.f32 "
                 "{%0,%1,%2,%3},{%4,%5,%6,%7},{%8,%9},{%0,%1,%2,%3};"
                 : "+f"(c[0]), "+f"(c[1]), "+f"(c[2]), "+f"(c[3])
                 : "r"(a[0]), "r"(a[1]), "r"(a[2]), "r"(a[3]), "r"(b[0]), "r"(b[1]));
}

// high-MLP absmax: 4 independent float4 chains per iteration
__global__ void absmax_kernel(const float* __restrict__ q, const float* __restrict__ k,
                              const float* __restrict__ v, int n) {
    const float* p = blockIdx.y == 0 ? q : (blockIdx.y == 1 ? k : v);
    const float4* p4 = (const float4*)p;
    int n4 = n >> 2;
    int stride = gridDim.x * blockDim.x;
    int i = blockIdx.x * blockDim.x + threadIdx.x;
    float m0 = 0.f, m1 = 0.f, m2 = 0.f, m3 = 0.f;
    for (; i + 3 * stride < n4; i += 4 * stride) {
        float4 a = p4[i];
        float4 bq = p4[i + stride];
        float4 c = p4[i + 2 * stride];
        float4 d = p4[i + 3 * stride];
        m0 = fmaxf(m0, fmaxf(fmaxf(fabsf(a.x), fabsf(a.y)), fmaxf(fabsf(a.z), fabsf(a.w))));
        m1 = fmaxf(m1, fmaxf(fmaxf(fabsf(bq.x), fabsf(bq.y)), fmaxf(fabsf(bq.z), fabsf(bq.w))));
        m2 = fmaxf(m2, fmaxf(fmaxf(fabsf(c.x), fabsf(c.y)), fmaxf(fabsf(c.z), fabsf(c.w))));
        m3 = fmaxf(m3, fmaxf(fmaxf(fabsf(d.x), fabsf(d.y)), fmaxf(fabsf(d.z), fabsf(d.w))));
    }
    for (; i < n4; i += stride) {
        float4 a = p4[i];
        m0 = fmaxf(m0, fmaxf(fmaxf(fabsf(a.x), fabsf(a.y)), fmaxf(fabsf(a.z), fabsf(a.w))));
    }
    float m = fmaxf(fmaxf(m0, m1), fmaxf(m2, m3));
    #pragma unroll
    for (int o = 16; o; o >>= 1) m = fmaxf(m, __shfl_xor_sync(0xffffffffu, m, o));
    if ((threadIdx.x & 31) == 0) atomicMax(&g_absmax[blockIdx.y], __float_as_uint(m));
}

__device__ __forceinline__ __half qd(float x, float inv) {
    __nv_fp8_storage_t f8 = __nv_cvt_float_to_fp8(x * inv, __NV_SATFINITE, __NV_E4M3);
    __half_raw hr = __nv_cvt_fp8_to_halfraw(f8, __NV_E4M3);
    return *reinterpret_cast<__half*>(&hr);
}

// streaming quantize + transpose for K and V only (Q is fused into fa)
__global__ void quant_kernel(const float* __restrict__ k, const float* __restrict__ v,
                             int total, int S) {
    int t = blockIdx.y + 1;
    const float* src = t == 1 ? k : v;
    __half* dst = t == 1 ? g_kh : g_vh;
    float inv = 448.0f / __uint_as_float(g_absmax[t]);
    size_t i = (size_t)blockIdx.x * blockDim.x + threadIdx.x;
    size_t n4 = ((size_t)total << 12) >> 2;
    if (i >= n4) return;
    float4 x = ((const float4*)src)[i];
    size_t e0 = i << 2;
    int token = (int)(e0 >> 12);
    int rem = (int)(e0 & 4095);
    int hh = rem >> 7;
    int d = rem & 127;
    int bb = token / S;
    int s = token - bb * S;
    size_t o = (((size_t)(bb * H_DIM + hh) * S + s) << 7) + d;
    __half rr[4];
    rr[0] = qd(x.x, inv); rr[1] = qd(x.y, inv);
    rr[2] = qd(x.z, inv); rr[3] = qd(x.w, inv);
    *(uint2*)(dst + o) = *(uint2*)rr;
}

// per-bh max K row norm: 16 threads per row, uint4 loads, 1 atomic per block
__global__ void kmax_kernel(int S) {
    __shared__ float sm[16];
    const int tid = threadIdx.x;
    const int row = blockIdx.x * 16 + (tid >> 4);
    const int seg = (tid & 15) * 8;
    uint4 u = *(const uint4*)(g_kh + (size_t)row * D_DIM + seg);
    const __half2* hp = (const __half2*)&u;
    float ss = 0.f;
    #pragma unroll
    for (int i = 0; i < 4; i++) {
        float2 f = __half22float2(hp[i]);
        ss += f.x * f.x + f.y * f.y;
    }
    #pragma unroll
    for (int o = 1; o < 16; o <<= 1) ss += __shfl_xor_sync(0xffffffffu, ss, o);
    if ((tid & 15) == 0) sm[tid >> 4] = ss;
    __syncthreads();
    if (tid == 0) {
        float m = sm[0];
        #pragma unroll
        for (int i = 1; i < 16; i++) m = fmaxf(m, sm[i]);
        atomicMax(&g_kmax[row / S], __float_as_uint(sqrtf(m)));
    }
}

__global__ __launch_bounds__(256, 1) void fa_kernel(float* __restrict__ out,
                                                    const float* __restrict__ qsrc, int S) {
    extern __shared__ __half smdyn[];
    __half (*KS)[ROWP] = (__half(*)[ROWP])smdyn;                    // 4 stages x 64 rows
    __half (*VS)[ROWP] = (__half(*)[ROWP])(smdyn + 256 * ROWP);

    const int bh = blockIdx.y;
    const int b = bh >> 5;
    const int h = bh & 31;
    const int qtile = gridDim.x - 1 - blockIdx.x;   // LPT: heaviest CTAs launch first
    const int q0 = qtile * BM;

    const size_t bhoff = (size_t)bh * S * D_DIM;
    const __half* Kg = g_kh + bhoff;
    const __half* Vg = g_vh + bhoff;

    const int tid = threadIdx.x;
    const int warp = tid >> 5;
    const int lane = tid & 31;
    const int l8 = lane & 7;
    const int g = lane >> 3;
    const int m0 = warp * 16;
    const float NEG_INF = __int_as_float(0xff800000);

    const float aq = __uint_as_float(g_absmax[0]) / 448.0f;
    const float ak = __uint_as_float(g_absmax[1]) / 448.0f;
    const float av = __uint_as_float(g_absmax[2]) / 448.0f;
    const float c1 = aq * ak * SM_SCALE * LOG2E;
    const float km = __uint_as_float(g_kmax[bh]);

    const int row0g = q0 + m0 + (lane >> 2);
    const int row1g = row0g + 8;

    // ---- fused Q: load fp32, quantize e4m3, store unscaled fp16 into KS rows 0..127 ----
    {
        const float invq = 448.0f / __uint_as_float(g_absmax[0]);
        const float* Qf = qsrc + ((size_t)(b * S + q0) * H_DIM + h) * D_DIM;
        #pragma unroll
        for (int it = 0; it < 16; it++) {
            int idx = tid + it * 256;
            int r = idx >> 5;
            int c4 = (idx & 31) * 4;
            float4 x = *(const float4*)(Qf + (size_t)r * H_DIM * D_DIM + c4);
            __half rr[4];
            rr[0] = qd(x.x, invq); rr[1] = qd(x.y, invq);
            rr[2] = qd(x.z, invq); rr[3] = qd(x.w, invq);
            *(uint2*)&KS[r][c4] = *(uint2*)rr;
        }
    }
    __syncthreads();
    uint32_t qf[8][4];
    #pragma unroll
    for (int kt = 0; kt < 8; kt++) {
        unsigned a = sptr(&KS[m0 + ((g & 1) << 3) + l8][kt * 16 + ((g & 2) << 2)]);
        ldsm4(qf[kt][0], qf[kt][1], qf[kt][2], qf[kt][3], a);
    }
    __syncthreads();

    // ---- in-register Q row norms ----
    float ss0 = 0.f, ss1 = 0.f;
    #pragma unroll
    for (int kt = 0; kt < 8; kt++) {
        float2 f0 = __half22float2(*(__half2*)&qf[kt][0]);
        float2 f1 = __half22float2(*(__half2*)&qf[kt][1]);
        float2 f2 = __half22float2(*(__half2*)&qf[kt][2]);
        float2 f3 = __half22float2(*(__half2*)&qf[kt][3]);
        ss0 += f0.x * f0.x + f0.y * f0.y + f2.x * f2.x + f2.y * f2.y;
        ss1 += f1.x * f1.x + f1.y * f1.y + f3.x * f3.x + f3.y * f3.y;
    }
    ss0 += __shfl_xor_sync(0xffffffffu, ss0, 1);
    ss0 += __shfl_xor_sync(0xffffffffu, ss0, 2);
    ss1 += __shfl_xor_sync(0xffffffffu, ss1, 1);
    ss1 += __shfl_xor_sync(0xffffffffu, ss1, 2);
    const float cadd0 = SHIFT - sqrtf(ss0) * km * c1 * 1.0001f;
    const float cadd1 = SHIFT - sqrtf(ss1) * km * c1 * 1.0001f;

    const int ntiles = 2 * qtile + 2;   // always even

    // ---- prologue: prefetch pair 0 ----
    {
        #pragma unroll
        for (int it = 0; it < 8; it++) {
            int idx = tid + it * 256;
            int r = idx >> 4;
            int c = (idx & 15) * 8;
            cpa16(sptr(&KS[r][c]), Kg + (size_t)r * D_DIM + c);
            cpa16(sptr(&VS[r][c]), Vg + (size_t)r * D_DIM + c);
        }
        asm volatile("cp.async.commit_group;");
    }

    float oacc[16][4];
    #pragma unroll
    for (int n = 0; n < 16; n++)
        #pragma unroll
        for (int e = 0; e < 4; e++) oacc[n][e] = 0.f;
    float lrow0 = 0.f, lrow1 = 0.f;

    for (int jj = 0; jj < ntiles; jj += 2) {
        const int stage = (jj >> 1) & 1;
        if (jj + 2 < ntiles) {
            const __half* Kj = Kg + (size_t)(jj + 2) * BN * D_DIM;
            const __half* Vj = Vg + (size_t)(jj + 2) * BN * D_DIM;
            const int nx = (stage ^ 1) * 128;
            #pragma unroll
            for (int it = 0; it < 8; it++) {
                int idx = tid + it * 256;
                int r = idx >> 4;
                int c = (idx & 15) * 8;
                cpa16(sptr(&KS[nx + r][c]), Kj + (size_t)r * D_DIM + c);
                cpa16(sptr(&VS[nx + r][c]), Vj + (size_t)r * D_DIM + c);
            }
            asm volatile("cp.async.commit_group;");
            asm volatile("cp.async.wait_group 1;");
        } else {
            asm volatile("cp.async.wait_group 0;");
        }
        __syncthreads();

        for (int j2 = 0; j2 < 2; j2++) {
            const int j = jj + j2;
            const int kb = stage * 128 + j2 * BN;
            const bool fullSkip = (j * BN > q0 + m0 + 15);
            if (fullSkip) continue;

            // ---- S = Q @ K^T ----
            float sacc[8][4];
            #pragma unroll
            for (int n8 = 0; n8 < 8; n8++)
                #pragma unroll
                for (int e = 0; e < 4; e++) sacc[n8][e] = 0.f;

            #pragma unroll
            for (int qq = 0; qq < 4; qq++) {
                uint32_t kbf[8][2][2];
                #pragma unroll
                for (int n8 = 0; n8 < 8; n8++) {
                    unsigned a = sptr(&KS[kb + (n8 << 3) + l8][qq * 32 + (g << 3)]);
                    ldsm4(kbf[n8][0][0], kbf[n8][0][1], kbf[n8][1][0], kbf[n8][1][1], a);
                }
                #pragma unroll
                for (int n8 = 0; n8 < 8; n8++)
                    mma16816(sacc[n8], qf[2 * qq], kbf[n8][0]);
                #pragma unroll
                for (int n8 = 0; n8 < 8; n8++)
                    mma16816(sacc[n8], qf[2 * qq + 1], kbf[n8][1]);
            }

            // ---- causal mask (only near-diagonal warp tiles) ----
            if (j * BN + BN - 1 > q0 + m0) {
                const int col0 = j * BN + ((lane & 3) << 1);
                #pragma unroll
                for (int n8 = 0; n8 < 8; n8++)
                    #pragma unroll
                    for (int e = 0; e < 4; e++) {
                        int col = col0 + (n8 << 3) + (e & 1);
                        int row = (e & 2) ? row1g : row0g;
                        if (col > row) sacc[n8][e] = NEG_INF;
                    }
            }

            // ---- fixed-bound softmax: no max, no rescale ----
            float ps0 = 0.f, ps1 = 0.f;
            uint32_t pf[4][4];
            #pragma unroll
            for (int n8 = 0; n8 < 8; n8++) {
                float p0 = ex2(fmaf(sacc[n8][0], c1, cadd0));
                float p1 = ex2(fmaf(sacc[n8][1], c1, cadd0));
                float p2 = ex2(fmaf(sacc[n8][2], c1, cadd1));
                float p3 = ex2(fmaf(sacc[n8][3], c1, cadd1));
                ps0 += p0 + p1;
                ps1 += p2 + p3;
                __half2 h01 = __floats2half2_rn(p0, p1);
                __half2 h23 = __floats2half2_rn(p2, p3);
                int kt = n8 >> 1;
                if (n8 & 1) {
                    pf[kt][2] = *reinterpret_cast<uint32_t*>(&h01);
                    pf[kt][3] = *reinterpret_cast<uint32_t*>(&h23);
                } else {
                    pf[kt][0] = *reinterpret_cast<uint32_t*>(&h01);
                    pf[kt][1] = *reinterpret_cast<uint32_t*>(&h23);
                }
            }
            lrow0 += ps0;
            lrow1 += ps1;

            // ---- O += P @ V ----
            #pragma unroll
            for (int kt = 0; kt < 4; kt++) {
                int k0 = kt << 4;
                #pragma unroll
                for (int e = 0; e < 8; e++) {
                    uint32_t r0, r1, r2, r3;
                    unsigned a = sptr(&VS[kb + k0 + ((g & 1) << 3) + l8][(e << 4) + ((g & 2) << 2)]);
                    ldsm4t(r0, r1, r2, r3, a);
                    uint32_t vb0[2] = {r0, r1}, vb1[2] = {r2, r3};
                    mma16816(oacc[2 * e], pf[kt], vb0);
                    mma16816(oacc[2 * e + 1], pf[kt], vb1);
                }
            }
        }
        __syncthreads();
    }

    // ---- epilogue ----
    lrow0 += __shfl_xor_sync(0xffffffffu, lrow0, 1);
    lrow0 += __shfl_xor_sync(0xffffffffu, lrow0, 2);
    lrow1 += __shfl_xor_sync(0xffffffffu, lrow1, 1);
    lrow1 += __shfl_xor_sync(0xffffffffu, lrow1, 2);
    float i0 = av / lrow0;
    float i1 = av / lrow1;
    size_t base0 = ((size_t)(b * S + row0g) * H_DIM + h) * D_DIM;
    size_t base1 = base0 + (size_t)8 * H_DIM * D_DIM;
    #pragma unroll
    for (int n = 0; n < 16; n++) {
        int col = (n << 3) + ((lane & 3) << 1);
        float2 v0 = {oacc[n][0] * i0, oacc[n][1] * i0};
        float2 v1 = {oacc[n][2] * i1, oacc[n][3] * i1};
        *(float2*)(out + base0 + col) = v0;
        *(float2*)(out + base1 + col) = v1;
    }
}

extern "C" void kernel_launch(void* const* d_in, const int* in_sizes, int n_in,
                              void* d_out, int out_size) {
    const float* q = (const float*)d_in[0];
    const float* k = (const float*)d_in[1];
    const float* v = (const float*)d_in[2];
    int n = in_sizes[0];
    int B = in_sizes[3] - 1;
    int total = n / (H_DIM * D_DIM);
    int S = total / B;
    int rows = total * H_DIM;

    cudaFuncSetAttribute(fa_kernel, cudaFuncAttributeMaxDynamicSharedMemorySize, SMEMSZ);

    absmax_kernel<<<dim3(592, 3), 256>>>(q, k, v, n);
    int n4 = n >> 2;
    quant_kernel<<<dim3((n4 + 255) / 256, 2), 256>>>(k, v, total, S);
    kmax_kernel<<<rows / 16, 256>>>(S);
    fa_kernel<<<dim3(S / BM, B * H_DIM), 256, SMEMSZ>>>((float*)d_out, q, S);
}

// round 14
// speedup vs baseline: 1.0443x; 1.0259x over previous
#include <cuda_runtime.h>
#include <cuda_fp16.h>
#include <cuda_fp8.h>
#include <stdint.h>

#define H_DIM 32
#define D_DIM 128
#define BM 128
#define BN 64
#define ROWP 136
#define SM_SCALE 0.08838834764831845f
#define LOG2E 1.4426950408889634f
#define SHIFT 14.0f
#define MAXTOT (4096*32*128)
#define SMEMSZ (2 * 256 * ROWP * 2)

__device__ __align__(16) __half g_kh[MAXTOT];
__device__ __align__(16) __half g_vh[MAXTOT];
__device__ unsigned g_absmax[3] = {0u, 0u, 0u};
__device__ unsigned g_kmax[128] = {};

__device__ __forceinline__ unsigned sptr(const void* p) {
    return (unsigned)__cvta_generic_to_shared(p);
}
__device__ __forceinline__ float ex2(float x) {
    float y; asm("ex2.approx.ftz.f32 %0,%1;" : "=f"(y) : "f"(x)); return y;
}
__device__ __forceinline__ void cpa16(unsigned s, const void* g) {
    asm volatile("cp.async.cg.shared.global [%0],[%1],16;" :: "r"(s), "l"(g));
}
__device__ __forceinline__ void ldsm4(uint32_t& r0, uint32_t& r1, uint32_t& r2, uint32_t& r3, unsigned a) {
    asm volatile("ldmatrix.sync.aligned.m8n8.x4.shared.b16 {%0,%1,%2,%3},[%4];"
                 : "=r"(r0), "=r"(r1), "=r"(r2), "=r"(r3) : "r"(a));
}
__device__ __forceinline__ void ldsm4t(uint32_t& r0, uint32_t& r1, uint32_t& r2, uint32_t& r3, unsigned a) {
    asm volatile("ldmatrix.sync.aligned.m8n8.x4.trans.shared.b16 {%0,%1,%2,%3},[%4];"
                 : "=r"(r0), "=r"(r1), "=r"(r2), "=r"(r3) : "r"(a));
}
__device__ __forceinline__ void mma16816(float* c, const uint32_t* a, const uint32_t* b) {
    asm volatile("mma.sync.aligned.m16n8k16.row.col.f32.f16.f16.f32 "
                 "{%0,%1,%2,%3},{%4,%5,%6,%7},{%8,%9},{%0,%1,%2,%3};"
                 : "+f"(c[0]), "+f"(c[1]), "+f"(c[2]), "+f"(c[3])
                 : "r"(a[0]), "r"(a[1]), "r"(a[2]), "r"(a[3]), "r"(b[0]), "r"(b[1]));
}

__device__ __forceinline__ float fmax4(float4 a) {
    return fmaxf(fmaxf(fabsf(a.x), fabsf(a.y)), fmaxf(fabsf(a.z), fabsf(a.w)));
}

// high-MLP absmax: 8 independent float4 chains per iteration
__global__ void absmax_kernel(const float* __restrict__ q, const float* __restrict__ k,
                              const float* __restrict__ v, int n) {
    const float* p = blockIdx.y == 0 ? q : (blockIdx.y == 1 ? k : v);
    const float4* p4 = (const float4*)p;
    int n4 = n >> 2;
    int stride = gridDim.x * blockDim.x;
    int i = blockIdx.x * blockDim.x + threadIdx.x;
    float m0 = 0.f, m1 = 0.f, m2 = 0.f, m3 = 0.f;
    float m4 = 0.f, m5 = 0.f, m6 = 0.f, m7 = 0.f;
    for (; i + 7 * stride < n4; i += 8 * stride) {
        m0 = fmaxf(m0, fmax4(p4[i]));
        m1 = fmaxf(m1, fmax4(p4[i + stride]));
        m2 = fmaxf(m2, fmax4(p4[i + 2 * stride]));
        m3 = fmaxf(m3, fmax4(p4[i + 3 * stride]));
        m4 = fmaxf(m4, fmax4(p4[i + 4 * stride]));
        m5 = fmaxf(m5, fmax4(p4[i + 5 * stride]));
        m6 = fmaxf(m6, fmax4(p4[i + 6 * stride]));
        m7 = fmaxf(m7, fmax4(p4[i + 7 * stride]));
    }
    for (; i < n4; i += stride) m0 = fmaxf(m0, fmax4(p4[i]));
    float m = fmaxf(fmaxf(fmaxf(m0, m1), fmaxf(m2, m3)),
                    fmaxf(fmaxf(m4, m5), fmaxf(m6, m7)));
    #pragma unroll
    for (int o = 16; o; o >>= 1) m = fmaxf(m, __shfl_xor_sync(0xffffffffu, m, o));
    if ((threadIdx.x & 31) == 0) atomicMax(&g_absmax[blockIdx.y], __float_as_uint(m));
}

__device__ __forceinline__ __half qd(float x, float inv) {
    __nv_fp8_storage_t f8 = __nv_cvt_float_to_fp8(x * inv, __NV_SATFINITE, __NV_E4M3);
    __half_raw hr = __nv_cvt_fp8_to_halfraw(f8, __NV_E4M3);
    return *reinterpret_cast<__half*>(&hr);
}

// streaming quantize + transpose for K and V: 8 elements/thread, uint4 stores
__global__ void quant_kernel(const float* __restrict__ k, const float* __restrict__ v,
                             int total, int S) {
    int t = blockIdx.y + 1;
    const float* src = t == 1 ? k : v;
    __half* dst = t == 1 ? g_kh : g_vh;
    float inv = 448.0f / __uint_as_float(g_absmax[t]);
    size_t i8 = (size_t)blockIdx.x * blockDim.x + threadIdx.x;   // 8-element chunk index
    size_t n8 = ((size_t)total << 12) >> 3;
    if (i8 >= n8) return;
    const float4* s4 = (const float4*)src;
    float4 x0 = s4[2 * i8];
    float4 x1 = s4[2 * i8 + 1];
    size_t e0 = i8 << 3;
    int token = (int)(e0 >> 12);
    int rem = (int)(e0 & 4095);
    int hh = rem >> 7;
    int d = rem & 127;
    int bb = token / S;
    int s = token - bb * S;
    size_t o = (((size_t)(bb * H_DIM + hh) * S + s) << 7) + d;
    __half rr[8];
    rr[0] = qd(x0.x, inv); rr[1] = qd(x0.y, inv);
    rr[2] = qd(x0.z, inv); rr[3] = qd(x0.w, inv);
    rr[4] = qd(x1.x, inv); rr[5] = qd(x1.y, inv);
    rr[6] = qd(x1.z, inv); rr[7] = qd(x1.w, inv);
    *(uint4*)(dst + o) = *(uint4*)rr;
}

// per-bh max K row norm: 16 threads per row, uint4 loads, 1 atomic per block
__global__ void kmax_kernel(int S) {
    __shared__ float sm[16];
    const int tid = threadIdx.x;
    const int row = blockIdx.x * 16 + (tid >> 4);
    const int seg = (tid & 15) * 8;
    uint4 u = *(const uint4*)(g_kh + (size_t)row * D_DIM + seg);
    const __half2* hp = (const __half2*)&u;
    float ss = 0.f;
    #pragma unroll
    for (int i = 0; i < 4; i++) {
        float2 f = __half22float2(hp[i]);
        ss += f.x * f.x + f.y * f.y;
    }
    #pragma unroll
    for (int o = 1; o < 16; o <<= 1) ss += __shfl_xor_sync(0xffffffffu, ss, o);
    if ((tid & 15) == 0) sm[tid >> 4] = ss;
    __syncthreads();
    if (tid == 0) {
        float m = sm[0];
        #pragma unroll
        for (int i = 1; i < 16; i++) m = fmaxf(m, sm[i]);
        atomicMax(&g_kmax[row / S], __float_as_uint(sqrtf(m)));
    }
}

__global__ __launch_bounds__(256, 1) void fa_kernel(float* __restrict__ out,
                                                    const float* __restrict__ qsrc, int S) {
    extern __shared__ __half smdyn[];
    __half (*KS)[ROWP] = (__half(*)[ROWP])smdyn;                    // 4 stages x 64 rows
    __half (*VS)[ROWP] = (__half(*)[ROWP])(smdyn + 256 * ROWP);

    const int bh = blockIdx.y;
    const int b = bh >> 5;
    const int h = bh & 31;
    const int qtile = gridDim.x - 1 - blockIdx.x;   // LPT: heaviest CTAs first
    const int q0 = qtile * BM;

    const size_t bhoff = (size_t)bh * S * D_DIM;
    const __half* Kg = g_kh + bhoff;
    const __half* Vg = g_vh + bhoff;

    const int tid = threadIdx.x;
    const int warp = tid >> 5;
    const int lane = tid & 31;
    const int l8 = lane & 7;
    const int g = lane >> 3;
    const int m0 = warp * 16;
    const float NEG_INF = __int_as_float(0xff800000);

    const float aq = __uint_as_float(g_absmax[0]) / 448.0f;
    const float ak = __uint_as_float(g_absmax[1]) / 448.0f;
    const float av = __uint_as_float(g_absmax[2]) / 448.0f;
    const float c1 = aq * ak * SM_SCALE * LOG2E;
    const float km = __uint_as_float(g_kmax[bh]);

    const int row0g = q0 + m0 + (lane >> 2);
    const int row1g = row0g + 8;

    // ---- fused Q: load fp32, quantize e4m3, store unscaled fp16 into KS rows 0..127 ----
    {
        const float invq = 448.0f / __uint_as_float(g_absmax[0]);
        const float* Qf = qsrc + ((size_t)(b * S + q0) * H_DIM + h) * D_DIM;
        #pragma unroll
        for (int it = 0; it < 16; it++) {
            int idx = tid + it * 256;
            int r = idx >> 5;
            int c4 = (idx & 31) * 4;
            float4 x = *(const float4*)(Qf + (size_t)r * H_DIM * D_DIM + c4);
            __half rr[4];
            rr[0] = qd(x.x, invq); rr[1] = qd(x.y, invq);
            rr[2] = qd(x.z, invq); rr[3] = qd(x.w, invq);
            *(uint2*)&KS[r][c4] = *(uint2*)rr;
        }
    }
    __syncthreads();
    uint32_t qf[8][4];
    #pragma unroll
    for (int kt = 0; kt < 8; kt++) {
        unsigned a = sptr(&KS[m0 + ((g & 1) << 3) + l8][kt * 16 + ((g & 2) << 2)]);
        ldsm4(qf[kt][0], qf[kt][1], qf[kt][2], qf[kt][3], a);
    }
    __syncthreads();

    // ---- in-register Q row norms ----
    float ss0 = 0.f, ss1 = 0.f;
    #pragma unroll
    for (int kt = 0; kt < 8; kt++) {
        float2 f0 = __half22float2(*(__half2*)&qf[kt][0]);
        float2 f1 = __half22float2(*(__half2*)&qf[kt][1]);
        float2 f2 = __half22float2(*(__half2*)&qf[kt][2]);
        float2 f3 = __half22float2(*(__half2*)&qf[kt][3]);
        ss0 += f0.x * f0.x + f0.y * f0.y + f2.x * f2.x + f2.y * f2.y;
        ss1 += f1.x * f1.x + f1.y * f1.y + f3.x * f3.x + f3.y * f3.y;
    }
    ss0 += __shfl_xor_sync(0xffffffffu, ss0, 1);
    ss0 += __shfl_xor_sync(0xffffffffu, ss0, 2);
    ss1 += __shfl_xor_sync(0xffffffffu, ss1, 1);
    ss1 += __shfl_xor_sync(0xffffffffu, ss1, 2);
    const float cadd0 = SHIFT - sqrtf(ss0) * km * c1 * 1.0001f;
    const float cadd1 = SHIFT - sqrtf(ss1) * km * c1 * 1.0001f;

    const int ntiles = 2 * qtile + 2;   // always even

    // ---- prologue: prefetch pair 0 ----
    {
        #pragma unroll
        for (int it = 0; it < 8; it++) {
            int idx = tid + it * 256;
            int r = idx >> 4;
            int c = (idx & 15) * 8;
            cpa16(sptr(&KS[r][c]), Kg + (size_t)r * D_DIM + c);
            cpa16(sptr(&VS[r][c]), Vg + (size_t)r * D_DIM + c);
        }
        asm volatile("cp.async.commit_group;");
    }

    float oacc[16][4];
    #pragma unroll
    for (int n = 0; n < 16; n++)
        #pragma unroll
        for (int e = 0; e < 4; e++) oacc[n][e] = 0.f;
    float lrow0 = 0.f, lrow1 = 0.f;

    for (int jj = 0; jj < ntiles; jj += 2) {
        const int stage = (jj >> 1) & 1;
        if (jj + 2 < ntiles) {
            const __half* Kj = Kg + (size_t)(jj + 2) * BN * D_DIM;
            const __half* Vj = Vg + (size_t)(jj + 2) * BN * D_DIM;
            const int nx = (stage ^ 1) * 128;
            #pragma unroll
            for (int it = 0; it < 8; it++) {
                int idx = tid + it * 256;
                int r = idx >> 4;
                int c = (idx & 15) * 8;
                cpa16(sptr(&KS[nx + r][c]), Kj + (size_t)r * D_DIM + c);
                cpa16(sptr(&VS[nx + r][c]), Vj + (size_t)r * D_DIM + c);
            }
            asm volatile("cp.async.commit_group;");
            asm volatile("cp.async.wait_group 1;");
        } else {
            asm volatile("cp.async.wait_group 0;");
        }
        __syncthreads();

        for (int j2 = 0; j2 < 2; j2++) {
            const int j = jj + j2;
            const int kb = stage * 128 + j2 * BN;
            const bool fullSkip = (j * BN > q0 + m0 + 15);
            if (fullSkip) continue;

            // ---- S = Q @ K^T ----
            float sacc[8][4];
            #pragma unroll
            for (int n8 = 0; n8 < 8; n8++)
                #pragma unroll
                for (int e = 0; e < 4; e++) sacc[n8][e] = 0.f;

            #pragma unroll
            for (int qq = 0; qq < 4; qq++) {
                uint32_t kbf[8][2][2];
                #pragma unroll
                for (int n8 = 0; n8 < 8; n8++) {
                    unsigned a = sptr(&KS[kb + (n8 << 3) + l8][qq * 32 + (g << 3)]);
                    ldsm4(kbf[n8][0][0], kbf[n8][0][1], kbf[n8][1][0], kbf[n8][1][1], a);
                }
                #pragma unroll
                for (int n8 = 0; n8 < 8; n8++)
                    mma16816(sacc[n8], qf[2 * qq], kbf[n8][0]);
                #pragma unroll
                for (int n8 = 0; n8 < 8; n8++)
                    mma16816(sacc[n8], qf[2 * qq + 1], kbf[n8][1]);
            }

            // ---- causal mask (only near-diagonal warp tiles) ----
            if (j * BN + BN - 1 > q0 + m0) {
                const int col0 = j * BN + ((lane & 3) << 1);
                #pragma unroll
                for (int n8 = 0; n8 < 8; n8++)
                    #pragma unroll
                    for (int e = 0; e < 4; e++) {
                        int col = col0 + (n8 << 3) + (e & 1);
                        int row = (e & 2) ? row1g : row0g;
                        if (col > row) sacc[n8][e] = NEG_INF;
                    }
            }

            // ---- fixed-bound softmax: no max, no rescale ----
            float ps0 = 0.f, ps1 = 0.f;
            uint32_t pf[4][4];
            #pragma unroll
            for (int n8 = 0; n8 < 8; n8++) {
                float p0 = ex2(fmaf(sacc[n8][0], c1, cadd0));
                float p1 = ex2(fmaf(sacc[n8][1], c1, cadd0));
                float p2 = ex2(fmaf(sacc[n8][2], c1, cadd1));
                float p3 = ex2(fmaf(sacc[n8][3], c1, cadd1));
                ps0 += p0 + p1;
                ps1 += p2 + p3;
                __half2 h01 = __floats2half2_rn(p0, p1);
                __half2 h23 = __floats2half2_rn(p2, p3);
                int kt = n8 >> 1;
                if (n8 & 1) {
                    pf[kt][2] = *reinterpret_cast<uint32_t*>(&h01);
                    pf[kt][3] = *reinterpret_cast<uint32_t*>(&h23);
                } else {
                    pf[kt][0] = *reinterpret_cast<uint32_t*>(&h01);
                    pf[kt][1] = *reinterpret_cast<uint32_t*>(&h23);
                }
            }
            lrow0 += ps0;
            lrow1 += ps1;

            // ---- O += P @ V ----
            #pragma unroll
            for (int kt = 0; kt < 4; kt++) {
                int k0 = kt << 4;
                #pragma unroll
                for (int e = 0; e < 8; e++) {
                    uint32_t r0, r1, r2, r3;
                    unsigned a = sptr(&VS[kb + k0 + ((g & 1) << 3) + l8][(e << 4) + ((g & 2) << 2)]);
                    ldsm4t(r0, r1, r2, r3, a);
                    uint32_t vb0[2] = {r0, r1}, vb1[2] = {r2, r3};
                    mma16816(oacc[2 * e], pf[kt], vb0);
                    mma16816(oacc[2 * e + 1], pf[kt], vb1);
                }
            }
        }
        __syncthreads();
    }

    // ---- epilogue ----
    lrow0 += __shfl_xor_sync(0xffffffffu, lrow0, 1);
    lrow0 += __shfl_xor_sync(0xffffffffu, lrow0, 2);
    lrow1 += __shfl_xor_sync(0xffffffffu, lrow1, 1);
    lrow1 += __shfl_xor_sync(0xffffffffu, lrow1, 2);
    float i0 = av / lrow0;
    float i1 = av / lrow1;
    size_t base0 = ((size_t)(b * S + row0g) * H_DIM + h) * D_DIM;
    size_t base1 = base0 + (size_t)8 * H_DIM * D_DIM;
    #pragma unroll
    for (int n = 0; n < 16; n++) {
        int col = (n << 3) + ((lane & 3) << 1);
        float2 v0 = {oacc[n][0] * i0, oacc[n][1] * i0};
        float2 v1 = {oacc[n][2] * i1, oacc[n][3] * i1};
        *(float2*)(out + base0 + col) = v0;
        *(float2*)(out + base1 + col) = v1;
    }
}

extern "C" void kernel_launch(void* const* d_in, const int* in_sizes, int n_in,
                              void* d_out, int out_size) {
    const float* q = (const float*)d_in[0];
    const float* k = (const float*)d_in[1];
    const float* v = (const float*)d_in[2];
    int n = in_sizes[0];
    int B = in_sizes[3] - 1;
    int total = n / (H_DIM * D_DIM);
    int S = total / B;
    int rows = total * H_DIM;

    cudaFuncSetAttribute(fa_kernel, cudaFuncAttributeMaxDynamicSharedMemorySize, SMEMSZ);

    absmax_kernel<<<dim3(592, 3), 256>>>(q, k, v, n);
    int n8 = n >> 3;
    quant_kernel<<<dim3((n8 + 255) / 256, 2), 256>>>(k, v, total, S);
    kmax_kernel<<<rows / 16, 256>>>(S);
    fa_kernel<<<dim3(S / BM, B * H_DIM), 256, SMEMSZ>>>((float*)d_out, q, S);
}

// round 15
// speedup vs baseline: 1.0449x; 1.0006x over previous
#include <cuda_runtime.h>
#include <cuda_fp16.h>
#include <cuda_fp8.h>
#include <stdint.h>

#define H_DIM 32
#define D_DIM 128
#define BM 128
#define BN 64
#define ROWP 136
#define SM_SCALE 0.08838834764831845f
#define LOG2E 1.4426950408889634f
#define SHIFT 14.0f
#define MAXTOT (4096*32*128)
#define SMEMSZ (2 * 256 * ROWP * 2)

__device__ __align__(16) __half g_kh[MAXTOT];
__device__ __align__(16) __half g_vh[MAXTOT];
__device__ unsigned g_absmax[3] = {0u, 0u, 0u};
__device__ unsigned g_kmax[128] = {};

__device__ __forceinline__ unsigned sptr(const void* p) {
    return (unsigned)__cvta_generic_to_shared(p);
}
__device__ __forceinline__ float ex2(float x) {
    float y; asm("ex2.approx.ftz.f32 %0,%1;" : "=f"(y) : "f"(x)); return y;
}
__device__ __forceinline__ void cpa16(unsigned s, const void* g) {
    asm volatile("cp.async.cg.shared.global [%0],[%1],16;" :: "r"(s), "l"(g));
}
__device__ __forceinline__ void ldsm4(uint32_t& r0, uint32_t& r1, uint32_t& r2, uint32_t& r3, unsigned a) {
    asm volatile("ldmatrix.sync.aligned.m8n8.x4.shared.b16 {%0,%1,%2,%3},[%4];"
                 : "=r"(r0), "=r"(r1), "=r"(r2), "=r"(r3) : "r"(a));
}
__device__ __forceinline__ void ldsm4t(uint32_t& r0, uint32_t& r1, uint32_t& r2, uint32_t& r3, unsigned a) {
    asm volatile("ldmatrix.sync.aligned.m8n8.x4.trans.shared.b16 {%0,%1,%2,%3},[%4];"
                 : "=r"(r0), "=r"(r1), "=r"(r2), "=r"(r3) : "r"(a));
}
__device__ __forceinline__ void mma16816(float* c, const uint32_t* a, const uint32_t* b) {
    asm volatile("mma.sync.aligned.m16n8k16.row.col.f32.f16.f16.f32 "
                 "{%0,%1,%2,%3},{%4,%5,%6,%7},{%8,%9},{%0,%1,%2,%3};"
                 : "+f"(c[0]), "+f"(c[1]), "+f"(c[2]), "+f"(c[3])
                 : "r"(a[0]), "r"(a[1]), "r"(a[2]), "r"(a[3]), "r"(b[0]), "r"(b[1]));
}

__device__ __forceinline__ float fmax4(float4 a) {
    return fmaxf(fmaxf(fabsf(a.x), fabsf(a.y)), fmaxf(fabsf(a.z), fabsf(a.w)));
}

// high-MLP absmax: 8 independent float4 chains per iteration
__global__ void absmax_kernel(const float* __restrict__ q, const float* __restrict__ k,
                              const float* __restrict__ v, int n) {
    const float* p = blockIdx.y == 0 ? q : (blockIdx.y == 1 ? k : v);
    const float4* p4 = (const float4*)p;
    int n4 = n >> 2;
    int stride = gridDim.x * blockDim.x;
    int i = blockIdx.x * blockDim.x + threadIdx.x;
    float m0 = 0.f, m1 = 0.f, m2 = 0.f, m3 = 0.f;
    float m4 = 0.f, m5 = 0.f, m6 = 0.f, m7 = 0.f;
    for (; i + 7 * stride < n4; i += 8 * stride) {
        m0 = fmaxf(m0, fmax4(p4[i]));
        m1 = fmaxf(m1, fmax4(p4[i + stride]));
        m2 = fmaxf(m2, fmax4(p4[i + 2 * stride]));
        m3 = fmaxf(m3, fmax4(p4[i + 3 * stride]));
        m4 = fmaxf(m4, fmax4(p4[i + 4 * stride]));
        m5 = fmaxf(m5, fmax4(p4[i + 5 * stride]));
        m6 = fmaxf(m6, fmax4(p4[i + 6 * stride]));
        m7 = fmaxf(m7, fmax4(p4[i + 7 * stride]));
    }
    for (; i < n4; i += stride) m0 = fmaxf(m0, fmax4(p4[i]));
    float m = fmaxf(fmaxf(fmaxf(m0, m1), fmaxf(m2, m3)),
                    fmaxf(fmaxf(m4, m5), fmaxf(m6, m7)));
    #pragma unroll
    for (int o = 16; o; o >>= 1) m = fmaxf(m, __shfl_xor_sync(0xffffffffu, m, o));
    if ((threadIdx.x & 31) == 0) atomicMax(&g_absmax[blockIdx.y], __float_as_uint(m));
}

__device__ __forceinline__ __half qd(float x, float inv) {
    __nv_fp8_storage_t f8 = __nv_cvt_float_to_fp8(x * inv, __NV_SATFINITE, __NV_E4M3);
    __half_raw hr = __nv_cvt_fp8_to_halfraw(f8, __NV_E4M3);
    return *reinterpret_cast<__half*>(&hr);
}

// streaming quantize + transpose for K and V: 16 elements/thread, 2x uint4 stores
__global__ void quant_kernel(const float* __restrict__ k, const float* __restrict__ v,
                             int total, int S) {
    int t = blockIdx.y + 1;
    const float* src = t == 1 ? k : v;
    __half* dst = t == 1 ? g_kh : g_vh;
    float inv = 448.0f / __uint_as_float(g_absmax[t]);
    size_t i16 = (size_t)blockIdx.x * blockDim.x + threadIdx.x;   // 16-element chunk index
    size_t n16 = ((size_t)total << 12) >> 4;
    if (i16 >= n16) return;
    const float4* s4 = (const float4*)src;
    float4 x0 = s4[4 * i16];
    float4 x1 = s4[4 * i16 + 1];
    float4 x2 = s4[4 * i16 + 2];
    float4 x3 = s4[4 * i16 + 3];
    size_t e0 = i16 << 4;
    int token = (int)(e0 >> 12);
    int rem = (int)(e0 & 4095);
    int hh = rem >> 7;
    int d = rem & 127;
    int bb = token / S;
    int s = token - bb * S;
    size_t o = (((size_t)(bb * H_DIM + hh) * S + s) << 7) + d;
    __half rr[16];
    rr[0]  = qd(x0.x, inv); rr[1]  = qd(x0.y, inv);
    rr[2]  = qd(x0.z, inv); rr[3]  = qd(x0.w, inv);
    rr[4]  = qd(x1.x, inv); rr[5]  = qd(x1.y, inv);
    rr[6]  = qd(x1.z, inv); rr[7]  = qd(x1.w, inv);
    rr[8]  = qd(x2.x, inv); rr[9]  = qd(x2.y, inv);
    rr[10] = qd(x2.z, inv); rr[11] = qd(x2.w, inv);
    rr[12] = qd(x3.x, inv); rr[13] = qd(x3.y, inv);
    rr[14] = qd(x3.z, inv); rr[15] = qd(x3.w, inv);
    *(uint4*)(dst + o) = *(uint4*)rr;
    *(uint4*)(dst + o + 8) = *(uint4*)(rr + 8);
}

// per-bh max K row norm: 16 threads per row, uint4 loads, 1 atomic per block
__global__ void kmax_kernel(int S) {
    __shared__ float sm[16];
    const int tid = threadIdx.x;
    const int row = blockIdx.x * 16 + (tid >> 4);
    const int seg = (tid & 15) * 8;
    uint4 u = *(const uint4*)(g_kh + (size_t)row * D_DIM + seg);
    const __half2* hp = (const __half2*)&u;
    float ss = 0.f;
    #pragma unroll
    for (int i = 0; i < 4; i++) {
        float2 f = __half22float2(hp[i]);
        ss += f.x * f.x + f.y * f.y;
    }
    #pragma unroll
    for (int o = 1; o < 16; o <<= 1) ss += __shfl_xor_sync(0xffffffffu, ss, o);
    if ((tid & 15) == 0) sm[tid >> 4] = ss;
    __syncthreads();
    if (tid == 0) {
        float m = sm[0];
        #pragma unroll
        for (int i = 1; i < 16; i++) m = fmaxf(m, sm[i]);
        atomicMax(&g_kmax[row / S], __float_as_uint(sqrtf(m)));
    }
}

__global__ __launch_bounds__(256, 1) void fa_kernel(float* __restrict__ out,
                                                    const float* __restrict__ qsrc, int S) {
    extern __shared__ __half smdyn[];
    __half (*KS)[ROWP] = (__half(*)[ROWP])smdyn;                    // 4 stages x 64 rows
    __half (*VS)[ROWP] = (__half(*)[ROWP])(smdyn + 256 * ROWP);

    const int bh = blockIdx.y;
    const int b = bh >> 5;
    const int h = bh & 31;
    const int qtile = gridDim.x - 1 - blockIdx.x;   // LPT: heaviest CTAs first
    const int q0 = qtile * BM;

    const size_t bhoff = (size_t)bh * S * D_DIM;
    const __half* Kg = g_kh + bhoff;
    const __half* Vg = g_vh + bhoff;

    const int tid = threadIdx.x;
    const int warp = tid >> 5;
    const int lane = tid & 31;
    const int l8 = lane & 7;
    const int g = lane >> 3;
    const int m0 = warp * 16;
    const float NEG_INF = __int_as_float(0xff800000);

    const float aq = __uint_as_float(g_absmax[0]) / 448.0f;
    const float ak = __uint_as_float(g_absmax[1]) / 448.0f;
    const float av = __uint_as_float(g_absmax[2]) / 448.0f;
    const float c1 = aq * ak * SM_SCALE * LOG2E;
    const float km = __uint_as_float(g_kmax[bh]);

    const int row0g = q0 + m0 + (lane >> 2);
    const int row1g = row0g + 8;

    // ---- fused Q: load fp32, quantize e4m3, store unscaled fp16 into KS rows 0..127 ----
    {
        const float invq = 448.0f / __uint_as_float(g_absmax[0]);
        const float* Qf = qsrc + ((size_t)(b * S + q0) * H_DIM + h) * D_DIM;
        #pragma unroll
        for (int it = 0; it < 16; it++) {
            int idx = tid + it * 256;
            int r = idx >> 5;
            int c4 = (idx & 31) * 4;
            float4 x = *(const float4*)(Qf + (size_t)r * H_DIM * D_DIM + c4);
            __half rr[4];
            rr[0] = qd(x.x, invq); rr[1] = qd(x.y, invq);
            rr[2] = qd(x.z, invq); rr[3] = qd(x.w, invq);
            *(uint2*)&KS[r][c4] = *(uint2*)rr;
        }
    }
    __syncthreads();
    uint32_t qf[8][4];
    #pragma unroll
    for (int kt = 0; kt < 8; kt++) {
        unsigned a = sptr(&KS[m0 + ((g & 1) << 3) + l8][kt * 16 + ((g & 2) << 2)]);
        ldsm4(qf[kt][0], qf[kt][1], qf[kt][2], qf[kt][3], a);
    }
    __syncthreads();

    // ---- in-register Q row norms ----
    float ss0 = 0.f, ss1 = 0.f;
    #pragma unroll
    for (int kt = 0; kt < 8; kt++) {
        float2 f0 = __half22float2(*(__half2*)&qf[kt][0]);
        float2 f1 = __half22float2(*(__half2*)&qf[kt][1]);
        float2 f2 = __half22float2(*(__half2*)&qf[kt][2]);
        float2 f3 = __half22float2(*(__half2*)&qf[kt][3]);
        ss0 += f0.x * f0.x + f0.y * f0.y + f2.x * f2.x + f2.y * f2.y;
        ss1 += f1.x * f1.x + f1.y * f1.y + f3.x * f3.x + f3.y * f3.y;
    }
    ss0 += __shfl_xor_sync(0xffffffffu, ss0, 1);
    ss0 += __shfl_xor_sync(0xffffffffu, ss0, 2);
    ss1 += __shfl_xor_sync(0xffffffffu, ss1, 1);
    ss1 += __shfl_xor_sync(0xffffffffu, ss1, 2);
    const float cadd0 = SHIFT - sqrtf(ss0) * km * c1 * 1.0001f;
    const float cadd1 = SHIFT - sqrtf(ss1) * km * c1 * 1.0001f;

    const int ntiles = 2 * qtile + 2;   // always even

    // ---- prologue: prefetch pair 0 ----
    {
        #pragma unroll
        for (int it = 0; it < 8; it++) {
            int idx = tid + it * 256;
            int r = idx >> 4;
            int c = (idx & 15) * 8;
            cpa16(sptr(&KS[r][c]), Kg + (size_t)r * D_DIM + c);
            cpa16(sptr(&VS[r][c]), Vg + (size_t)r * D_DIM + c);
        }
        asm volatile("cp.async.commit_group;");
    }

    float oacc[16][4];
    #pragma unroll
    for (int n = 0; n < 16; n++)
        #pragma unroll
        for (int e = 0; e < 4; e++) oacc[n][e] = 0.f;
    float lrow0 = 0.f, lrow1 = 0.f;

    for (int jj = 0; jj < ntiles; jj += 2) {
        const int stage = (jj >> 1) & 1;
        if (jj + 2 < ntiles) {
            const __half* Kj = Kg + (size_t)(jj + 2) * BN * D_DIM;
            const __half* Vj = Vg + (size_t)(jj + 2) * BN * D_DIM;
            const int nx = (stage ^ 1) * 128;
            #pragma unroll
            for (int it = 0; it < 8; it++) {
                int idx = tid + it * 256;
                int r = idx >> 4;
                int c = (idx & 15) * 8;
                cpa16(sptr(&KS[nx + r][c]), Kj + (size_t)r * D_DIM + c);
                cpa16(sptr(&VS[nx + r][c]), Vj + (size_t)r * D_DIM + c);
            }
            asm volatile("cp.async.commit_group;");
            asm volatile("cp.async.wait_group 1;");
        } else {
            asm volatile("cp.async.wait_group 0;");
        }
        __syncthreads();

        for (int j2 = 0; j2 < 2; j2++) {
            const int j = jj + j2;
            const int kb = stage * 128 + j2 * BN;
            const bool fullSkip = (j * BN > q0 + m0 + 15);
            if (fullSkip) continue;

            // ---- S = Q @ K^T ----
            float sacc[8][4];
            #pragma unroll
            for (int n8 = 0; n8 < 8; n8++)
                #pragma unroll
                for (int e = 0; e < 4; e++) sacc[n8][e] = 0.f;

            #pragma unroll
            for (int qq = 0; qq < 4; qq++) {
                uint32_t kbf[8][2][2];
                #pragma unroll
                for (int n8 = 0; n8 < 8; n8++) {
                    unsigned a = sptr(&KS[kb + (n8 << 3) + l8][qq * 32 + (g << 3)]);
                    ldsm4(kbf[n8][0][0], kbf[n8][0][1], kbf[n8][1][0], kbf[n8][1][1], a);
                }
                #pragma unroll
                for (int n8 = 0; n8 < 8; n8++)
                    mma16816(sacc[n8], qf[2 * qq], kbf[n8][0]);
                #pragma unroll
                for (int n8 = 0; n8 < 8; n8++)
                    mma16816(sacc[n8], qf[2 * qq + 1], kbf[n8][1]);
            }

            // ---- causal mask (only near-diagonal warp tiles) ----
            if (j * BN + BN - 1 > q0 + m0) {
                const int col0 = j * BN + ((lane & 3) << 1);
                #pragma unroll
                for (int n8 = 0; n8 < 8; n8++)
                    #pragma unroll
                    for (int e = 0; e < 4; e++) {
                        int col = col0 + (n8 << 3) + (e & 1);
                        int row = (e & 2) ? row1g : row0g;
                        if (col > row) sacc[n8][e] = NEG_INF;
                    }
            }

            // ---- fixed-bound softmax: no max, no rescale ----
            float ps0 = 0.f, ps1 = 0.f;
            uint32_t pf[4][4];
            #pragma unroll
            for (int n8 = 0; n8 < 8; n8++) {
                float p0 = ex2(fmaf(sacc[n8][0], c1, cadd0));
                float p1 = ex2(fmaf(sacc[n8][1], c1, cadd0));
                float p2 = ex2(fmaf(sacc[n8][2], c1, cadd1));
                float p3 = ex2(fmaf(sacc[n8][3], c1, cadd1));
                ps0 += p0 + p1;
                ps1 += p2 + p3;
                __half2 h01 = __floats2half2_rn(p0, p1);
                __half2 h23 = __floats2half2_rn(p2, p3);
                int kt = n8 >> 1;
                if (n8 & 1) {
                    pf[kt][2] = *reinterpret_cast<uint32_t*>(&h01);
                    pf[kt][3] = *reinterpret_cast<uint32_t*>(&h23);
                } else {
                    pf[kt][0] = *reinterpret_cast<uint32_t*>(&h01);
                    pf[kt][1] = *reinterpret_cast<uint32_t*>(&h23);
                }
            }
            lrow0 += ps0;
            lrow1 += ps1;

            // ---- O += P @ V ----
            #pragma unroll
            for (int kt = 0; kt < 4; kt++) {
                int k0 = kt << 4;
                #pragma unroll
                for (int e = 0; e < 8; e++) {
                    uint32_t r0, r1, r2, r3;
                    unsigned a = sptr(&VS[kb + k0 + ((g & 1) << 3) + l8][(e << 4) + ((g & 2) << 2)]);
                    ldsm4t(r0, r1, r2, r3, a);
                    uint32_t vb0[2] = {r0, r1}, vb1[2] = {r2, r3};
                    mma16816(oacc[2 * e], pf[kt], vb0);
                    mma16816(oacc[2 * e + 1], pf[kt], vb1);
                }
            }
        }
        __syncthreads();
    }

    // ---- epilogue ----
    lrow0 += __shfl_xor_sync(0xffffffffu, lrow0, 1);
    lrow0 += __shfl_xor_sync(0xffffffffu, lrow0, 2);
    lrow1 += __shfl_xor_sync(0xffffffffu, lrow1, 1);
    lrow1 += __shfl_xor_sync(0xffffffffu, lrow1, 2);
    float i0 = av / lrow0;
    float i1 = av / lrow1;
    size_t base0 = ((size_t)(b * S + row0g) * H_DIM + h) * D_DIM;
    size_t base1 = base0 + (size_t)8 * H_DIM * D_DIM;
    #pragma unroll
    for (int n = 0; n < 16; n++) {
        int col = (n << 3) + ((lane & 3) << 1);
        float2 v0 = {oacc[n][0] * i0, oacc[n][1] * i0};
        float2 v1 = {oacc[n][2] * i1, oacc[n][3] * i1};
        *(float2*)(out + base0 + col) = v0;
        *(float2*)(out + base1 + col) = v1;
    }
}

extern "C" void kernel_launch(void* const* d_in, const int* in_sizes, int n_in,
                              void* d_out, int out_size) {
    const float* q = (const float*)d_in[0];
    const float* k = (const float*)d_in[1];
    const float* v = (const float*)d_in[2];
    int n = in_sizes[0];
    int B = in_sizes[3] - 1;
    int total = n / (H_DIM * D_DIM);
    int S = total / B;
    int rows = total * H_DIM;

    cudaFuncSetAttribute(fa_kernel, cudaFuncAttributeMaxDynamicSharedMemorySize, SMEMSZ);

    absmax_kernel<<<dim3(592, 3), 256>>>(q, k, v, n);
    int n16 = n >> 4;
    quant_kernel<<<dim3((n16 + 255) / 256, 2), 256>>>(k, v, total, S);
    kmax_kernel<<<rows / 16, 256>>>(S);
    fa_kernel<<<dim3(S / BM, B * H_DIM), 256, SMEMSZ>>>((float*)d_out, q, S);
}

// round 16
// speedup vs baseline: 1.0900x; 1.0431x over previous
#include <cuda_runtime.h>
#include <cuda_fp16.h>
#include <cuda_fp8.h>
#include <stdint.h>

#define H_DIM 32
#define D_DIM 128
#define BM 128
#define BN 64
#define ROWP 136
#define SM_SCALE 0.08838834764831845f
#define LOG2E 1.4426950408889634f
#define SHIFT 14.0f
#define MAXTOT (4096*32*128)
#define SMEMSZ (2 * 256 * ROWP * 2)

__device__ __align__(16) __half g_kh[MAXTOT];
__device__ __align__(16) __half g_vh[MAXTOT];
__device__ unsigned g_absmax[3] = {0u, 0u, 0u};
__device__ unsigned g_kmax[128] = {};

__device__ __forceinline__ unsigned sptr(const void* p) {
    return (unsigned)__cvta_generic_to_shared(p);
}
__device__ __forceinline__ float ex2(float x) {
    float y; asm("ex2.approx.ftz.f32 %0,%1;" : "=f"(y) : "f"(x)); return y;
}
__device__ __forceinline__ void cpa16(unsigned s, const void* g) {
    asm volatile("cp.async.cg.shared.global [%0],[%1],16;" :: "r"(s), "l"(g));
}
__device__ __forceinline__ void ldsm4(uint32_t& r0, uint32_t& r1, uint32_t& r2, uint32_t& r3, unsigned a) {
    asm volatile("ldmatrix.sync.aligned.m8n8.x4.shared.b16 {%0,%1,%2,%3},[%4];"
                 : "=r"(r0), "=r"(r1), "=r"(r2), "=r"(r3) : "r"(a));
}
__device__ __forceinline__ void ldsm4t(uint32_t& r0, uint32_t& r1, uint32_t& r2, uint32_t& r3, unsigned a) {
    asm volatile("ldmatrix.sync.aligned.m8n8.x4.trans.shared.b16 {%0,%1,%2,%3},[%4];"
                 : "=r"(r0), "=r"(r1), "=r"(r2), "=r"(r3) : "r"(a));
}
__device__ __forceinline__ void mma16816(float* c, const uint32_t* a, const uint32_t* b) {
    asm volatile("mma.sync.aligned.m16n8k16.row.col.f32.f16.f16.f32 "
                 "{%0,%1,%2,%3},{%4,%5,%6,%7},{%8,%9},{%0,%1,%2,%3};"
                 : "+f"(c[0]), "+f"(c[1]), "+f"(c[2]), "+f"(c[3])
                 : "r"(a[0]), "r"(a[1]), "r"(a[2]), "r"(a[3]), "r"(b[0]), "r"(b[1]));
}

__device__ __forceinline__ float fmax4(float4 a) {
    return fmaxf(fmaxf(fabsf(a.x), fabsf(a.y)), fmaxf(fabsf(a.z), fabsf(a.w)));
}

// high-MLP absmax: 8 independent float4 chains per iteration
__global__ void absmax_kernel(const float* __restrict__ q, const float* __restrict__ k,
                              const float* __restrict__ v, int n) {
    const float* p = blockIdx.y == 0 ? q : (blockIdx.y == 1 ? k : v);
    const float4* p4 = (const float4*)p;
    int n4 = n >> 2;
    int stride = gridDim.x * blockDim.x;
    int i = blockIdx.x * blockDim.x + threadIdx.x;
    float m0 = 0.f, m1 = 0.f, m2 = 0.f, m3 = 0.f;
    float m4 = 0.f, m5 = 0.f, m6 = 0.f, m7 = 0.f;
    for (; i + 7 * stride < n4; i += 8 * stride) {
        m0 = fmaxf(m0, fmax4(p4[i]));
        m1 = fmaxf(m1, fmax4(p4[i + stride]));
        m2 = fmaxf(m2, fmax4(p4[i + 2 * stride]));
        m3 = fmaxf(m3, fmax4(p4[i + 3 * stride]));
        m4 = fmaxf(m4, fmax4(p4[i + 4 * stride]));
        m5 = fmaxf(m5, fmax4(p4[i + 5 * stride]));
        m6 = fmaxf(m6, fmax4(p4[i + 6 * stride]));
        m7 = fmaxf(m7, fmax4(p4[i + 7 * stride]));
    }
    for (; i < n4; i += stride) m0 = fmaxf(m0, fmax4(p4[i]));
    float m = fmaxf(fmaxf(fmaxf(m0, m1), fmaxf(m2, m3)),
                    fmaxf(fmaxf(m4, m5), fmaxf(m6, m7)));
    #pragma unroll
    for (int o = 16; o; o >>= 1) m = fmaxf(m, __shfl_xor_sync(0xffffffffu, m, o));
    if ((threadIdx.x & 31) == 0) atomicMax(&g_absmax[blockIdx.y], __float_as_uint(m));
}

__device__ __forceinline__ __half qd(float x, float inv) {
    __nv_fp8_storage_t f8 = __nv_cvt_float_to_fp8(x * inv, __NV_SATFINITE, __NV_E4M3);
    __half_raw hr = __nv_cvt_fp8_to_halfraw(f8, __NV_E4M3);
    return *reinterpret_cast<__half*>(&hr);
}

// output-major quantize + transpose for K and V; K branch also emits per-bh max row norm.
// Each block covers 32 consecutive destination rows (same bh since 32 | S).
// Thread t: local_row = t>>3, d0 = (t&7)*16  (8 threads per 128-elem row).
__global__ void quant_kernel(const float* __restrict__ k, const float* __restrict__ v,
                             int S) {
    __shared__ float snorm[32];
    const int t = blockIdx.y;          // 0 = K, 1 = V
    const float* src = t == 0 ? k : v;
    __half* dst = t == 0 ? g_kh : g_vh;
    const float inv = 448.0f / __uint_as_float(g_absmax[t + 1]);

    const int tid = threadIdx.x;
    const int lrow = tid >> 3;
    const int d0 = (tid & 7) * 16;
    const int grow = blockIdx.x * 32 + lrow;       // global dst row = bh*S + s
    const int bh = grow / S;
    const int s = grow - bh * S;
    const int bb = bh >> 5;
    const int hh = bh & 31;

    const float* sp = src + ((size_t)(bb * S + s) * H_DIM + hh) * D_DIM + d0;
    const float4* s4 = (const float4*)sp;
    float4 x0 = s4[0], x1 = s4[1], x2 = s4[2], x3 = s4[3];

    __half rr[16];
    rr[0]  = qd(x0.x, inv); rr[1]  = qd(x0.y, inv);
    rr[2]  = qd(x0.z, inv); rr[3]  = qd(x0.w, inv);
    rr[4]  = qd(x1.x, inv); rr[5]  = qd(x1.y, inv);
    rr[6]  = qd(x1.z, inv); rr[7]  = qd(x1.w, inv);
    rr[8]  = qd(x2.x, inv); rr[9]  = qd(x2.y, inv);
    rr[10] = qd(x2.z, inv); rr[11] = qd(x2.w, inv);
    rr[12] = qd(x3.x, inv); rr[13] = qd(x3.y, inv);
    rr[14] = qd(x3.z, inv); rr[15] = qd(x3.w, inv);

    __half* dp = dst + ((size_t)grow << 7) + d0;
    *(uint4*)dp = *(uint4*)rr;
    *(uint4*)(dp + 8) = *(uint4*)(rr + 8);

    if (t == 0) {
        // per-row ssq of quantized values -> per-bh max (1 atomic per block)
        float ss = 0.f;
        #pragma unroll
        for (int i = 0; i < 8; i++) {
            float2 f = __half22float2(*(__half2*)&rr[2 * i]);
            ss += f.x * f.x + f.y * f.y;
        }
        ss += __shfl_xor_sync(0xffffffffu, ss, 1);
        ss += __shfl_xor_sync(0xffffffffu, ss, 2);
        ss += __shfl_xor_sync(0xffffffffu, ss, 4);
        if ((tid & 7) == 0) snorm[lrow] = ss;
        __syncthreads();
        if (tid == 0) {
            float m = snorm[0];
            #pragma unroll
            for (int i = 1; i < 32; i++) m = fmaxf(m, snorm[i]);
            atomicMax(&g_kmax[bh], __float_as_uint(sqrtf(m)));
        }
    }
}

__global__ __launch_bounds__(256, 1) void fa_kernel(float* __restrict__ out,
                                                    const float* __restrict__ qsrc, int S) {
    extern __shared__ __half smdyn[];
    __half (*KS)[ROWP] = (__half(*)[ROWP])smdyn;                    // 4 stages x 64 rows
    __half (*VS)[ROWP] = (__half(*)[ROWP])(smdyn + 256 * ROWP);

    const int bh = blockIdx.y;
    const int b = bh >> 5;
    const int h = bh & 31;
    const int qtile = gridDim.x - 1 - blockIdx.x;   // LPT: heaviest CTAs first
    const int q0 = qtile * BM;

    const size_t bhoff = (size_t)bh * S * D_DIM;
    const __half* Kg = g_kh + bhoff;
    const __half* Vg = g_vh + bhoff;

    const int tid = threadIdx.x;
    const int warp = tid >> 5;
    const int lane = tid & 31;
    const int l8 = lane & 7;
    const int g = lane >> 3;
    const int m0 = warp * 16;
    const float NEG_INF = __int_as_float(0xff800000);

    const float aq = __uint_as_float(g_absmax[0]) / 448.0f;
    const float ak = __uint_as_float(g_absmax[1]) / 448.0f;
    const float av = __uint_as_float(g_absmax[2]) / 448.0f;
    const float c1 = aq * ak * SM_SCALE * LOG2E;
    const float km = __uint_as_float(g_kmax[bh]);

    const int row0g = q0 + m0 + (lane >> 2);
    const int row1g = row0g + 8;

    // ---- fused Q: load fp32, quantize e4m3, store unscaled fp16 into KS rows 0..127 ----
    {
        const float invq = 448.0f / __uint_as_float(g_absmax[0]);
        const float* Qf = qsrc + ((size_t)(b * S + q0) * H_DIM + h) * D_DIM;
        #pragma unroll
        for (int it = 0; it < 16; it++) {
            int idx = tid + it * 256;
            int r = idx >> 5;
            int c4 = (idx & 31) * 4;
            float4 x = *(const float4*)(Qf + (size_t)r * H_DIM * D_DIM + c4);
            __half rr[4];
            rr[0] = qd(x.x, invq); rr[1] = qd(x.y, invq);
            rr[2] = qd(x.z, invq); rr[3] = qd(x.w, invq);
            *(uint2*)&KS[r][c4] = *(uint2*)rr;
        }
    }
    __syncthreads();
    uint32_t qf[8][4];
    #pragma unroll
    for (int kt = 0; kt < 8; kt++) {
        unsigned a = sptr(&KS[m0 + ((g & 1) << 3) + l8][kt * 16 + ((g & 2) << 2)]);
        ldsm4(qf[kt][0], qf[kt][1], qf[kt][2], qf[kt][3], a);
    }
    __syncthreads();

    // ---- in-register Q row norms ----
    float ss0 = 0.f, ss1 = 0.f;
    #pragma unroll
    for (int kt = 0; kt < 8; kt++) {
        float2 f0 = __half22float2(*(__half2*)&qf[kt][0]);
        float2 f1 = __half22float2(*(__half2*)&qf[kt][1]);
        float2 f2 = __half22float2(*(__half2*)&qf[kt][2]);
        float2 f3 = __half22float2(*(__half2*)&qf[kt][3]);
        ss0 += f0.x * f0.x + f0.y * f0.y + f2.x * f2.x + f2.y * f2.y;
        ss1 += f1.x * f1.x + f1.y * f1.y + f3.x * f3.x + f3.y * f3.y;
    }
    ss0 += __shfl_xor_sync(0xffffffffu, ss0, 1);
    ss0 += __shfl_xor_sync(0xffffffffu, ss0, 2);
    ss1 += __shfl_xor_sync(0xffffffffu, ss1, 1);
    ss1 += __shfl_xor_sync(0xffffffffu, ss1, 2);
    const float cadd0 = SHIFT - sqrtf(ss0) * km * c1 * 1.0001f;
    const float cadd1 = SHIFT - sqrtf(ss1) * km * c1 * 1.0001f;

    const int ntiles = 2 * qtile + 2;   // always even

    // ---- prologue: prefetch pair 0 ----
    {
        #pragma unroll
        for (int it = 0; it < 8; it++) {
            int idx = tid + it * 256;
            int r = idx >> 4;
            int c = (idx & 15) * 8;
            cpa16(sptr(&KS[r][c]), Kg + (size_t)r * D_DIM + c);
            cpa16(sptr(&VS[r][c]), Vg + (size_t)r * D_DIM + c);
        }
        asm volatile("cp.async.commit_group;");
    }

    float oacc[16][4];
    #pragma unroll
    for (int n = 0; n < 16; n++)
        #pragma unroll
        for (int e = 0; e < 4; e++) oacc[n][e] = 0.f;
    float lrow0 = 0.f, lrow1 = 0.f;

    for (int jj = 0; jj < ntiles; jj += 2) {
        const int stage = (jj >> 1) & 1;
        if (jj + 2 < ntiles) {
            const __half* Kj = Kg + (size_t)(jj + 2) * BN * D_DIM;
            const __half* Vj = Vg + (size_t)(jj + 2) * BN * D_DIM;
            const int nx = (stage ^ 1) * 128;
            #pragma unroll
            for (int it = 0; it < 8; it++) {
                int idx = tid + it * 256;
                int r = idx >> 4;
                int c = (idx & 15) * 8;
                cpa16(sptr(&KS[nx + r][c]), Kj + (size_t)r * D_DIM + c);
                cpa16(sptr(&VS[nx + r][c]), Vj + (size_t)r * D_DIM + c);
            }
            asm volatile("cp.async.commit_group;");
            asm volatile("cp.async.wait_group 1;");
        } else {
            asm volatile("cp.async.wait_group 0;");
        }
        __syncthreads();

        for (int j2 = 0; j2 < 2; j2++) {
            const int j = jj + j2;
            const int kb = stage * 128 + j2 * BN;
            const bool fullSkip = (j * BN > q0 + m0 + 15);
            if (fullSkip) continue;

            // ---- S = Q @ K^T ----
            float sacc[8][4];
            #pragma unroll
            for (int n8 = 0; n8 < 8; n8++)
                #pragma unroll
                for (int e = 0; e < 4; e++) sacc[n8][e] = 0.f;

            #pragma unroll
            for (int qq = 0; qq < 4; qq++) {
                uint32_t kbf[8][2][2];
                #pragma unroll
                for (int n8 = 0; n8 < 8; n8++) {
                    unsigned a = sptr(&KS[kb + (n8 << 3) + l8][qq * 32 + (g << 3)]);
                    ldsm4(kbf[n8][0][0], kbf[n8][0][1], kbf[n8][1][0], kbf[n8][1][1], a);
                }
                #pragma unroll
                for (int n8 = 0; n8 < 8; n8++)
                    mma16816(sacc[n8], qf[2 * qq], kbf[n8][0]);
                #pragma unroll
                for (int n8 = 0; n8 < 8; n8++)
                    mma16816(sacc[n8], qf[2 * qq + 1], kbf[n8][1]);
            }

            // ---- causal mask (only near-diagonal warp tiles) ----
            if (j * BN + BN - 1 > q0 + m0) {
                const int col0 = j * BN + ((lane & 3) << 1);
                #pragma unroll
                for (int n8 = 0; n8 < 8; n8++)
                    #pragma unroll
                    for (int e = 0; e < 4; e++) {
                        int col = col0 + (n8 << 3) + (e & 1);
                        int row = (e & 2) ? row1g : row0g;
                        if (col > row) sacc[n8][e] = NEG_INF;
                    }
            }

            // ---- fixed-bound softmax: no max, no rescale ----
            float ps0 = 0.f, ps1 = 0.f;
            uint32_t pf[4][4];
            #pragma unroll
            for (int n8 = 0; n8 < 8; n8++) {
                float p0 = ex2(fmaf(sacc[n8][0], c1, cadd0));
                float p1 = ex2(fmaf(sacc[n8][1], c1, cadd0));
                float p2 = ex2(fmaf(sacc[n8][2], c1, cadd1));
                float p3 = ex2(fmaf(sacc[n8][3], c1, cadd1));
                ps0 += p0 + p1;
                ps1 += p2 + p3;
                __half2 h01 = __floats2half2_rn(p0, p1);
                __half2 h23 = __floats2half2_rn(p2, p3);
                int kt = n8 >> 1;
                if (n8 & 1) {
                    pf[kt][2] = *reinterpret_cast<uint32_t*>(&h01);
                    pf[kt][3] = *reinterpret_cast<uint32_t*>(&h23);
                } else {
                    pf[kt][0] = *reinterpret_cast<uint32_t*>(&h01);
                    pf[kt][1] = *reinterpret_cast<uint32_t*>(&h23);
                }
            }
            lrow0 += ps0;
            lrow1 += ps1;

            // ---- O += P @ V ----
            #pragma unroll
            for (int kt = 0; kt < 4; kt++) {
                int k0 = kt << 4;
                #pragma unroll
                for (int e = 0; e < 8; e++) {
                    uint32_t r0, r1, r2, r3;
                    unsigned a = sptr(&VS[kb + k0 + ((g & 1) << 3) + l8][(e << 4) + ((g & 2) << 2)]);
                    ldsm4t(r0, r1, r2, r3, a);
                    uint32_t vb0[2] = {r0, r1}, vb1[2] = {r2, r3};
                    mma16816(oacc[2 * e], pf[kt], vb0);
                    mma16816(oacc[2 * e + 1], pf[kt], vb1);
                }
            }
        }
        __syncthreads();
    }

    // ---- epilogue ----
    lrow0 += __shfl_xor_sync(0xffffffffu, lrow0, 1);
    lrow0 += __shfl_xor_sync(0xffffffffu, lrow0, 2);
    lrow1 += __shfl_xor_sync(0xffffffffu, lrow1, 1);
    lrow1 += __shfl_xor_sync(0xffffffffu, lrow1, 2);
    float i0 = av / lrow0;
    float i1 = av / lrow1;
    size_t base0 = ((size_t)(b * S + row0g) * H_DIM + h) * D_DIM;
    size_t base1 = base0 + (size_t)8 * H_DIM * D_DIM;
    #pragma unroll
    for (int n = 0; n < 16; n++) {
        int col = (n << 3) + ((lane & 3) << 1);
        float2 v0 = {oacc[n][0] * i0, oacc[n][1] * i0};
        float2 v1 = {oacc[n][2] * i1, oacc[n][3] * i1};
        *(float2*)(out + base0 + col) = v0;
        *(float2*)(out + base1 + col) = v1;
    }
}

extern "C" void kernel_launch(void* const* d_in, const int* in_sizes, int n_in,
                              void* d_out, int out_size) {
    const float* q = (const float*)d_in[0];
    const float* k = (const float*)d_in[1];
    const float* v = (const float*)d_in[2];
    int n = in_sizes[0];
    int B = in_sizes[3] - 1;
    int total = n / (H_DIM * D_DIM);
    int S = total / B;
    int rows = total * H_DIM;

    cudaFuncSetAttribute(fa_kernel, cudaFuncAttributeMaxDynamicSharedMemorySize, SMEMSZ);

    absmax_kernel<<<dim3(592, 3), 256>>>(q, k, v, n);
    quant_kernel<<<dim3(rows / 32, 2), 256>>>(k, v, S);
    fa_kernel<<<dim3(S / BM, B * H_DIM), 256, SMEMSZ>>>((float*)d_out, q, S);
}